// round 15
// baseline (speedup 1.0000x reference)
#include <cuda_runtime.h>
#include <cuda_bf16.h>
#include <math.h>
#include <stdint.h>

typedef unsigned int u32;

#define HIDDEN 2048
#define NH     16
#define HD     128
#define KVC    512
#define QC     1536
#define RD     64
#define BATCH  2
#define SEQ    2048
#define AD     192
#define MR     (BATCH*SEQ)
#define BHN    (BATCH*NH)

// ---------------- scratch ----------------
__device__ float g_kc  [MR*NH*HD];
__device__ float g_v   [MR*NH*HD];
__device__ float g_kr  [MR*NH*RD];
__device__ float g_quc [MR*NH*HD];
__device__ float g_qr  [MR*NH*RD];
__device__ float g_sinT[SEQ*32];
__device__ float g_cosT[SEQ*32];

__device__ __nv_bfloat16 g_xh  [(size_t)MR*HIDDEN];
__device__ __nv_bfloat16 g_xl  [(size_t)MR*HIDDEN];
__device__ __nv_bfloat16 g_kvch[(size_t)MR*KVC];
__device__ __nv_bfloat16 g_kvcl[(size_t)MR*KVC];
__device__ __nv_bfloat16 g_qch [(size_t)MR*QC];
__device__ __nv_bfloat16 g_qcl [(size_t)MR*QC];
__device__ __nv_bfloat16 g_ctxh[(size_t)MR*NH*HD];
__device__ __nv_bfloat16 g_ctxl[(size_t)MR*NH*HD];

#define WT_TOTAL 15728640
__device__ __nv_bfloat16 g_Wth[WT_TOTAL];
__device__ __nv_bfloat16 g_Wtl[WT_TOTAL];
#define OFF_KVD 0L
#define OFF_QD  1048576L
#define OFF_KU  4194304L
#define OFF_VU  5242880L
#define OFF_KR  6291456L
#define OFF_QU  6815744L
#define OFF_QR  9961472L
#define OFF_OUT 11534336L

__device__ __nv_bfloat16 g_Qph[(size_t)BHN*SEQ*AD];
__device__ __nv_bfloat16 g_Qpl[(size_t)BHN*SEQ*AD];
__device__ __nv_bfloat16 g_Kph[(size_t)BHN*SEQ*AD];
__device__ __nv_bfloat16 g_Kpl[(size_t)BHN*SEQ*AD];
__device__ u32 g_Vph[(size_t)BHN*HD*(SEQ/2)];
__device__ u32 g_Vpl[(size_t)BHN*HD*(SEQ/2)];

// ---------------- helpers ----------------
__device__ __forceinline__ float fexp(float x) {
    if (x < -80.f) return 0.f;
    float y = x * 1.4426950408889634f;
    float r = rintf(y);
    float f = y - r;
    float p = 1.3333558e-3f;
    p = fmaf(p, f, 9.6181291e-3f);
    p = fmaf(p, f, 5.5504109e-2f);
    p = fmaf(p, f, 2.4022651e-1f);
    p = fmaf(p, f, 6.9314718e-1f);
    p = fmaf(p, f, 1.0f);
    int n = (int)r;
    return p * __int_as_float((n + 127) << 23);
}
__device__ __forceinline__ u32 pk2(__nv_bfloat16 a, __nv_bfloat16 b) {
    return (u32)__bfloat16_as_ushort(a) | ((u32)__bfloat16_as_ushort(b) << 16);
}
__device__ __forceinline__ u32 pk2f(float a, float b) {
    return pk2(__float2bfloat16(a), __float2bfloat16(b));
}
__device__ __forceinline__ void mma_bf16(float* c, const u32* a, const u32* b) {
    asm volatile(
        "mma.sync.aligned.m16n8k16.row.col.f32.bf16.bf16.f32 "
        "{%0,%1,%2,%3}, {%4,%5,%6,%7}, {%8,%9}, {%0,%1,%2,%3};"
        : "+f"(c[0]), "+f"(c[1]), "+f"(c[2]), "+f"(c[3])
        : "r"(a[0]), "r"(a[1]), "r"(a[2]), "r"(a[3]), "r"(b[0]), "r"(b[1]));
}
__device__ __forceinline__ void ldm4(u32* r, u32 saddr) {
    asm volatile("ldmatrix.sync.aligned.m8n8.x4.shared.b16 {%0,%1,%2,%3}, [%4];"
        : "=r"(r[0]), "=r"(r[1]), "=r"(r[2]), "=r"(r[3]) : "r"(saddr));
}
__device__ __forceinline__ u32 smem_u32p(const void* p) {
    u32 a;
    asm("{ .reg .u64 t; cvta.to.shared.u64 t, %1; cvt.u32.u64 %0, t; }" : "=r"(a) : "l"(p));
    return a;
}
__device__ __forceinline__ void cpa16(u32 s, const void* g) {
    asm volatile("cp.async.cg.shared.global [%0], [%1], 16;" :: "r"(s), "l"(g));
}
#define CPC()  asm volatile("cp.async.commit_group;" ::: "memory")
#define CPW0() asm volatile("cp.async.wait_group 0;" ::: "memory")

// ---------------- prep ----------------
struct WD { const float* src; long off; int K; int N; };
struct WP { WD d[8]; };

__global__ void prep_kernel(WP p, const float* __restrict__ x) {
    int z = blockIdx.z;
    if (z < 8) {
        WD d = p.d[z];
        int ktiles = d.K >> 5, ntiles = d.N >> 5;
        int tile = blockIdx.x;
        if (tile >= ktiles * ntiles) return;
        int k0 = (tile % ktiles) << 5;
        int n0 = (tile / ktiles) << 5;
        __shared__ float tb[32][33];
        int lx = threadIdx.x & 31, ly = threadIdx.x >> 5;
        for (int i = ly; i < 32; i += 8)
            tb[i][lx] = d.src[(size_t)(k0 + i) * d.N + n0 + lx];
        __syncthreads();
        for (int i = ly; i < 32; i += 8) {
            float v = tb[lx][i];
            __nv_bfloat16 hi = __float2bfloat16(v);
            size_t o = d.off + (size_t)(n0 + i) * d.K + k0 + lx;
            g_Wth[o] = hi;
            g_Wtl[o] = __float2bfloat16(v - __bfloat162float(hi));
        }
    } else if (z == 8) {
        for (long long i = (long long)blockIdx.x * 256 + threadIdx.x;
             i < (long long)MR * HIDDEN; i += 4096LL * 256) {
            float v = x[i];
            __nv_bfloat16 hi = __float2bfloat16(v);
            g_xh[i] = hi;
            g_xl[i] = __float2bfloat16(v - __bfloat162float(hi));
        }
    } else {
        int i = blockIdx.x * 256 + threadIdx.x;
        if (i < SEQ * 32) {
            int s = i >> 5, pp = i & 31;
            double inv = pow(10000.0, -((double)pp) / 32.0);
            double a = (double)s * inv;
            g_sinT[i] = (float)sin(a);
            g_cosT[i] = (float)cos(a);
        }
    }
}

// ---------------- bf16-split HMMA multi-segment GEMM ----------------
struct GSeg {
    const __nv_bfloat16* aph; const __nv_bfloat16* apl;
    long woff; const float* bias;
    float* outf; __nv_bfloat16* oh; __nv_bfloat16* ol;
    int N; int K;
};
struct GP { GSeg s[5]; };

#define GBUF 2560   // 128 rows * 20 u32

__global__ __launch_bounds__(256, 2) void hgemm_multi(GP p)
{
    extern __shared__ u32 smg[];
    const u32 sb = smem_u32p(smg);
    const int tid = threadIdx.x, lane = tid & 31, w = tid >> 5;
    const int wm = w & 3, wn = w >> 2;
    const int g = lane >> 2, t = lane & 3;
    const int row0 = blockIdx.y * 128;
    int cg = blockIdx.x * 128;

    GSeg sg = p.s[0];
    int col0 = cg;
    #pragma unroll
    for (int i = 0; i < 5; i++) {
        if (p.s[i].N > 0 && col0 < p.s[i].N) { sg = p.s[i]; break; }
        col0 -= p.s[i].N;
    }
    const int K = sg.K;
    const __nv_bfloat16* Aph = sg.aph;
    const __nv_bfloat16* Apl = sg.apl;
    const __nv_bfloat16* Bph = g_Wth + sg.woff;
    const __nv_bfloat16* Bpl = g_Wtl + sg.woff;

    const int lr = tid >> 2;
    const int lc = (tid & 3) * 4;

    float acc[2][8][4];
    #pragma unroll
    for (int mt = 0; mt < 2; mt++)
        #pragma unroll
        for (int nt = 0; nt < 8; nt++)
            #pragma unroll
            for (int j = 0; j < 4; j++) acc[mt][nt][j] = 0.f;

    const u32 arow = wm * 32 + (lane & 15);
    const u32 aoff = ((lane >> 4) << 2);
    const u32 krow = (lane & 7) | ((lane >> 4) << 3);
    const u32 koff = ((lane >> 3) & 1) << 2;

    const int KT = K >> 5;

    // prologue: stage 0
    #pragma unroll
    for (int j = 0; j < 2; j++) {
        int r = lr + j * 64;
        u32 so = sb + (r * 20 + lc) * 4;
        cpa16(so,              Aph + (size_t)(row0 + r) * K + lc * 2);
        cpa16(so + GBUF * 4,   Apl + (size_t)(row0 + r) * K + lc * 2);
        cpa16(so + GBUF * 8,   Bph + (size_t)(col0 + r) * K + lc * 2);
        cpa16(so + GBUF * 12,  Bpl + (size_t)(col0 + r) * K + lc * 2);
    }
    CPC();

    for (int kt = 0; kt < KT; kt++) {
        CPW0();
        __syncthreads();
        if (kt + 1 < KT) {
            int k0 = (kt + 1) << 5;
            u32 stb = sb + ((kt + 1) & 1) * GBUF * 16;
            #pragma unroll
            for (int j = 0; j < 2; j++) {
                int r = lr + j * 64;
                u32 so = stb + (r * 20 + lc) * 4;
                cpa16(so,              Aph + (size_t)(row0 + r) * K + k0 + lc * 2);
                cpa16(so + GBUF * 4,   Apl + (size_t)(row0 + r) * K + k0 + lc * 2);
                cpa16(so + GBUF * 8,   Bph + (size_t)(col0 + r) * K + k0 + lc * 2);
                cpa16(so + GBUF * 12,  Bpl + (size_t)(col0 + r) * K + k0 + lc * 2);
            }
            CPC();
        }

        const u32 stb = sb + (kt & 1) * GBUF * 16;
        const u32 bA  = stb + (arow * 20 + aoff) * 4;
        const u32 bAl = bA + GBUF * 4;
        const u32 bB  = stb + GBUF * 8 + ((wn * 64 + krow) * 20 + koff) * 4;
        const u32 bBl = bB + GBUF * 4;

        #pragma unroll
        for (int ks = 0; ks < 2; ks++) {
            u32 ah[2][4], al[2][4];
            ldm4(ah[0], bA + ks * 32);
            ldm4(ah[1], bA + 1280 + ks * 32);
            ldm4(al[0], bAl + ks * 32);
            ldm4(al[1], bAl + 1280 + ks * 32);
            #pragma unroll
            for (int ntp = 0; ntp < 4; ntp++) {
                u32 bh[4], bl[4];
                ldm4(bh, bB + ntp * 1280 + ks * 32);
                ldm4(bl, bBl + ntp * 1280 + ks * 32);
                // interleave 4 independent accumulator chains
                mma_bf16(acc[0][2*ntp],   ah[0], bh);
                mma_bf16(acc[1][2*ntp],   ah[1], bh);
                mma_bf16(acc[0][2*ntp+1], ah[0], bh + 2);
                mma_bf16(acc[1][2*ntp+1], ah[1], bh + 2);
                mma_bf16(acc[0][2*ntp],   ah[0], bl);
                mma_bf16(acc[1][2*ntp],   ah[1], bl);
                mma_bf16(acc[0][2*ntp+1], ah[0], bl + 2);
                mma_bf16(acc[1][2*ntp+1], ah[1], bl + 2);
                mma_bf16(acc[0][2*ntp],   al[0], bh);
                mma_bf16(acc[1][2*ntp],   al[1], bh);
                mma_bf16(acc[0][2*ntp+1], al[0], bh + 2);
                mma_bf16(acc[1][2*ntp+1], al[1], bh + 2);
            }
        }
    }

    // epilogue
    #pragma unroll
    for (int mt = 0; mt < 2; mt++) {
        int r0 = row0 + wm * 32 + mt * 16 + g;
        int r1 = r0 + 8;
        #pragma unroll
        for (int nt = 0; nt < 8; nt++) {
            int c = col0 + wn * 64 + nt * 8 + 2 * t;
            float b0 = sg.bias[c], b1 = sg.bias[c + 1];
            float v00 = acc[mt][nt][0] + b0, v01 = acc[mt][nt][1] + b1;
            float v10 = acc[mt][nt][2] + b0, v11 = acc[mt][nt][3] + b1;
            if (sg.outf) {
                float2 w0; w0.x = v00; w0.y = v01;
                float2 w1; w1.x = v10; w1.y = v11;
                *(float2*)&sg.outf[(size_t)r0 * sg.N + c] = w0;
                *(float2*)&sg.outf[(size_t)r1 * sg.N + c] = w1;
            } else {
                __nv_bfloat16 h00 = __float2bfloat16(v00), h01 = __float2bfloat16(v01);
                __nv_bfloat16 h10 = __float2bfloat16(v10), h11 = __float2bfloat16(v11);
                *(u32*)&sg.oh[(size_t)r0 * sg.N + c] = pk2(h00, h01);
                *(u32*)&sg.ol[(size_t)r0 * sg.N + c] =
                    pk2f(v00 - __bfloat162float(h00), v01 - __bfloat162float(h01));
                *(u32*)&sg.oh[(size_t)r1 * sg.N + c] = pk2(h10, h11);
                *(u32*)&sg.ol[(size_t)r1 * sg.N + c] =
                    pk2f(v10 - __bfloat162float(h10), v11 - __bfloat162float(h11));
            }
        }
    }
}

// ---------------- unified pack kernel (Q pre-scaled by 1/sqrt(192)) ----------------
#define QK_SCALE 0.07216878364870323f

__global__ void pack_all()
{
    int job = blockIdx.y;
    if (job < 2) {
        const float* cflat = job ? g_quc : g_kc;
        const float* rflat = job ? g_qr  : g_kr;
        __nv_bfloat16* oh  = job ? g_Qph : g_Kph;
        __nv_bfloat16* ol  = job ? g_Qpl : g_Kpl;
        long long idx = (long long)blockIdx.x * blockDim.x + threadIdx.x;
        const long long total = (long long)BHN * SEQ * AD;
        if (idx >= total) return;
        int d = (int)(idx % AD);
        int s = (int)((idx / AD) % SEQ);
        int h = (int)((idx / ((long long)AD * SEQ)) % NH);
        int b = (int)(idx / ((long long)AD * SEQ * NH));
        int row = b * SEQ + s;
        float val;
        if (d < HD) {
            val = cflat[(size_t)row * (NH*HD) + h * HD + d];
        } else {
            int j = d - HD, p = j >> 1;
            const float* rp = rflat + (size_t)row * (NH*RD) + h * RD + 2 * p;
            float x0 = rp[0], x1 = rp[1];
            float cc = g_cosT[s * 32 + p], sn = g_sinT[s * 32 + p];
            val = (j & 1) ? (x0 * sn + x1 * cc) : (x0 * cc - x1 * sn);
        }
        if (job) val *= QK_SCALE;
        __nv_bfloat16 hi = __float2bfloat16(val);
        oh[idx] = hi;
        ol[idx] = __float2bfloat16(val - __bfloat162float(hi));
    } else {
        int tile = blockIdx.x;
        if (tile >= 64 * 4 * BHN) return;
        int s0 = (tile & 63) * 32;
        int d0 = ((tile >> 6) & 3) * 32;
        int bh = tile >> 8;
        int b = bh >> 4, h = bh & 15;
        int lx = threadIdx.x & 31, ly = threadIdx.x >> 5;
        __shared__ float tilebuf[32][33];
        for (int i = ly; i < 32; i += 8) {
            int s = s0 + i;
            tilebuf[i][lx] = g_v[(size_t)(b * SEQ + s) * (NH*HD) + h * HD + d0 + lx];
        }
        __syncthreads();
        for (int i = ly; i < 32; i += 8) {
            if (lx < 16) {
                int d = d0 + i;
                float v0 = tilebuf[2 * lx][i];
                float v1 = tilebuf[2 * lx + 1][i];
                __nv_bfloat16 h0 = __float2bfloat16(v0);
                __nv_bfloat16 h1 = __float2bfloat16(v1);
                size_t o = ((size_t)bh * HD + d) * (SEQ/2) + (s0 >> 1) + lx;
                g_Vph[o] = pk2(h0, h1);
                g_Vpl[o] = pk2(__float2bfloat16(v0 - __bfloat162float(h0)),
                               __float2bfloat16(v1 - __bfloat162float(h1)));
            }
        }
    }
}

// ---------------- cp.async pipelined mma attention (BN=32, Q-hi in regs) -----------
#define ATQH 0
#define ATQL 12800
#define ATK  25600
#define ATV  38400
#define ATSM 48640

__global__ __launch_bounds__(256) void attn_mma_kernel()
{
    extern __shared__ u32 sm[];
    const u32 sb   = smem_u32p(sm);
    const int tid  = threadIdx.x;
    const int lane = tid & 31;
    const int w    = tid >> 5;
    const int g    = lane >> 2;
    const int t4   = lane & 3;
    const int qt   = (int)gridDim.x - 1 - (int)blockIdx.x;
    const int bh   = blockIdx.y;
    const int b    = bh >> 4, h = bh & 15;
    const int q0   = qt * 128;
    const int T    = 4 * qt + 4;

    const uint4* Qh4 = (const uint4*)g_Qph;
    const uint4* Ql4 = (const uint4*)g_Qpl;
    const uint4* Kh4 = (const uint4*)g_Kph;
    const uint4* Kl4 = (const uint4*)g_Kpl;

    // ---- Q tile ----
    for (int i = tid; i < 3072; i += 256) {
        int r = i / 24, c = i - r * 24;
        size_t gs = ((size_t)bh * SEQ + q0 + r) * 24 + c;
        *(uint4*)&sm[ATQH + r * 100 + c * 4] = Qh4[gs];
        *(uint4*)&sm[ATQL + r * 100 + c * 4] = Ql4[gs];
    }

    // ---- prologue: cp.async K/V stage 0 ----
    {
        #pragma unroll
        for (int j = 0; j < 3; j++) {
            int i = tid + j * 256;
            int r = i / 24, c = i - r * 24;
            u32 so = sb + (ATK + r * 100 + c * 4) * 4;
            cpa16(so,            &Kh4[((size_t)bh * SEQ + r) * 24 + c]);
            cpa16(so + 3200 * 4, &Kl4[((size_t)bh * SEQ + r) * 24 + c]);
        }
        #pragma unroll
        for (int j = 0; j < 2; j++) {
            int i = tid + j * 256;
            int r = i >> 2, c = i & 3;
            u32 so = sb + (ATV + r * 20 + c * 4) * 4;
            cpa16(so,            &g_Vph[(((size_t)bh * HD + r) * 256 + c) * 4]);
            cpa16(so + 2560 * 4, &g_Vpl[(((size_t)bh * HD + r) * 256 + c) * 4]);
        }
        CPC();
    }

    const u32 qrow = w * 16 + (lane & 15);
    const u32 qoff = (lane >> 4) << 2;
    const u32 aQh = sb + (ATQH + qrow * 100 + qoff) * 4;
    const u32 aQl = sb + (ATQL + qrow * 100 + qoff) * 4;
    const u32 krow = (lane & 7) | ((lane >> 4) << 3);
    const u32 koff = ((lane >> 3) & 1) << 2;

    // ---- hoist Q-hi fragments into registers (loop-invariant) ----
    __syncthreads();
    u32 qh[12][4];
    #pragma unroll
    for (int ks = 0; ks < 12; ks++) ldm4(qh[ks], aQh + ks * 32);

    float m0 = -1e30f, m1 = -1e30f, l0 = 0.f, l1 = 0.f;
    float O[16][4];
    #pragma unroll
    for (int nt = 0; nt < 16; nt++)
        #pragma unroll
        for (int j = 0; j < 4; j++) O[nt][j] = 0.f;

    const int row0g = q0 + w * 16 + g;
    const int row1g = row0g + 8;
    const int wrow_max = q0 + w * 16 + 15;

    for (int kt = 0; kt < T; kt++) {
        CPW0();
        __syncthreads();
        if (kt + 1 < T) {
            int kn = (kt + 1) * 32;
            u32 skb = sb + (ATK + ((kt + 1) & 1) * 6400) * 4;
            u32 svb = sb + (ATV + ((kt + 1) & 1) * 5120) * 4;
            #pragma unroll
            for (int j = 0; j < 3; j++) {
                int i = tid + j * 256;
                int r = i / 24, c = i - r * 24;
                u32 so = skb + (r * 100 + c * 4) * 4;
                cpa16(so,            &Kh4[((size_t)bh * SEQ + kn + r) * 24 + c]);
                cpa16(so + 3200 * 4, &Kl4[((size_t)bh * SEQ + kn + r) * 24 + c]);
            }
            #pragma unroll
            for (int j = 0; j < 2; j++) {
                int i = tid + j * 256;
                int r = i >> 2, c = i & 3;
                u32 so = svb + (r * 20 + c * 4) * 4;
                cpa16(so,            &g_Vph[((size_t)bh * HD + r) * 1024 + (kt + 1) * 16 + c * 4]);
                cpa16(so + 2560 * 4, &g_Vpl[((size_t)bh * HD + r) * 1024 + (kt + 1) * 16 + c * 4]);
            }
            CPC();
        }

        const int k0 = kt * 32;
        if (k0 > wrow_max) continue;
        const int ng = min(2, (wrow_max - k0) / 16 + 1);

        const u32 aK  = sb + (ATK + (kt & 1) * 6400 + krow * 100 + koff) * 4;
        const u32 aKl = aK + 3200 * 4;
        const u32 aV  = sb + (ATV + (kt & 1) * 5120 + krow * 20 + koff) * 4;
        const u32 aVl = aV + 2560 * 4;

        // ---- scores ----
        float sc[4][4];
        #pragma unroll
        for (int nt = 0; nt < 4; nt++)
            #pragma unroll
            for (int j = 0; j < 4; j++) sc[nt][j] = 0.f;

        if (ng == 2) {
            #pragma unroll
            for (int ks = 0; ks < 12; ks++) {
                u32 al[4];
                ldm4(al, aQl + ks * 32);
                #pragma unroll
                for (int ntp = 0; ntp < 2; ntp++) {
                    u32 kh[4], kl[4];
                    ldm4(kh, aK + ntp * 6400 + ks * 32);
                    ldm4(kl, aKl + ntp * 6400 + ks * 32);
                    mma_bf16(sc[2*ntp],   qh[ks], kh);
                    mma_bf16(sc[2*ntp+1], qh[ks], kh + 2);
                    mma_bf16(sc[2*ntp],   qh[ks], kl);
                    mma_bf16(sc[2*ntp+1], qh[ks], kl + 2);
                    mma_bf16(sc[2*ntp],   al, kh);
                    mma_bf16(sc[2*ntp+1], al, kh + 2);
                }
            }
        } else {
            #pragma unroll
            for (int ks = 0; ks < 12; ks++) {
                u32 al[4];
                ldm4(al, aQl + ks * 32);
                u32 kh[4], kl[4];
                ldm4(kh, aK + ks * 32);
                ldm4(kl, aKl + ks * 32);
                mma_bf16(sc[0], qh[ks], kh);
                mma_bf16(sc[1], qh[ks], kh + 2);
                mma_bf16(sc[0], qh[ks], kl);
                mma_bf16(sc[1], qh[ks], kl + 2);
                mma_bf16(sc[0], al, kh);
                mma_bf16(sc[1], al, kh + 2);
            }
        }

        // ---- mask + online softmax (scores pre-scaled via Q) ----
        const bool diag = (k0 + 31) > row0g;
        float mt0 = -1e30f, mt1 = -1e30f;
        #pragma unroll
        for (int nt = 0; nt < 4; nt++) {
            int c0 = k0 + nt * 8 + 2 * t4, c1 = c0 + 1;
            if (diag) {
                if (c0 > row0g) sc[nt][0] = -1e30f;
                if (c1 > row0g) sc[nt][1] = -1e30f;
                if (c0 > row1g) sc[nt][2] = -1e30f;
                if (c1 > row1g) sc[nt][3] = -1e30f;
            }
            mt0 = fmaxf(mt0, fmaxf(sc[nt][0], sc[nt][1]));
            mt1 = fmaxf(mt1, fmaxf(sc[nt][2], sc[nt][3]));
        }
        mt0 = fmaxf(mt0, __shfl_xor_sync(0xffffffffu, mt0, 1));
        mt0 = fmaxf(mt0, __shfl_xor_sync(0xffffffffu, mt0, 2));
        mt1 = fmaxf(mt1, __shfl_xor_sync(0xffffffffu, mt1, 1));
        mt1 = fmaxf(mt1, __shfl_xor_sync(0xffffffffu, mt1, 2));

        float mn0 = fmaxf(m0, mt0), mn1 = fmaxf(m1, mt1);
        float a0 = fexp(m0 - mn0), a1 = fexp(m1 - mn1);
        m0 = mn0; m1 = mn1;

        float s0 = 0.f, s1 = 0.f;
        #pragma unroll
        for (int nt = 0; nt < 4; nt++) {
            sc[nt][0] = fexp(sc[nt][0] - mn0);
            sc[nt][1] = fexp(sc[nt][1] - mn0);
            sc[nt][2] = fexp(sc[nt][2] - mn1);
            sc[nt][3] = fexp(sc[nt][3] - mn1);
            s0 += sc[nt][0] + sc[nt][1];
            s1 += sc[nt][2] + sc[nt][3];
        }
        s0 += __shfl_xor_sync(0xffffffffu, s0, 1);
        s0 += __shfl_xor_sync(0xffffffffu, s0, 2);
        s1 += __shfl_xor_sync(0xffffffffu, s1, 1);
        s1 += __shfl_xor_sync(0xffffffffu, s1, 2);
        l0 = l0 * a0 + s0;
        l1 = l1 * a1 + s1;

        #pragma unroll
        for (int nt = 0; nt < 16; nt++) {
            O[nt][0] *= a0; O[nt][1] *= a0;
            O[nt][2] *= a1; O[nt][3] *= a1;
        }

        // ---- O += P V ----
        #pragma unroll
        for (int ks = 0; ks < 2; ks++) {
            if (ks >= ng) break;
            u32 ah[4], al[4];
            #pragma unroll
            for (int half = 0; half < 2; half++) {
                float v0 = sc[2*ks + half][0], v1 = sc[2*ks + half][1];
                float v2 = sc[2*ks + half][2], v3 = sc[2*ks + half][3];
                __nv_bfloat16 h0 = __float2bfloat16(v0), h1 = __float2bfloat16(v1);
                __nv_bfloat16 h2 = __float2bfloat16(v2), h3 = __float2bfloat16(v3);
                ah[half*2 + 0] = pk2(h0, h1);
                ah[half*2 + 1] = pk2(h2, h3);
                al[half*2 + 0] = pk2f(v0 - __bfloat162float(h0), v1 - __bfloat162float(h1));
                al[half*2 + 1] = pk2f(v2 - __bfloat162float(h2), v3 - __bfloat162float(h3));
            }
            #pragma unroll
            for (int ntp = 0; ntp < 8; ntp++) {
                u32 vh[4], vl[4];
                ldm4(vh, aV + ntp * 1280 + ks * 32);
                ldm4(vl, aVl + ntp * 1280 + ks * 32);
                mma_bf16(O[2*ntp],   ah, vh);
                mma_bf16(O[2*ntp+1], ah, vh + 2);
                mma_bf16(O[2*ntp],   ah, vl);
                mma_bf16(O[2*ntp+1], ah, vl + 2);
                mma_bf16(O[2*ntp],   al, vh);
                mma_bf16(O[2*ntp+1], al, vh + 2);
            }
        }
    }

    // ---- epilogue ----
    float inv0 = 1.f / l0, inv1 = 1.f / l1;
    size_t base0 = ((size_t)(b * SEQ) + row0g) * (NH*HD) + h * HD;
    size_t base1 = ((size_t)(b * SEQ) + row1g) * (NH*HD) + h * HD;
    #pragma unroll
    for (int nt = 0; nt < 16; nt++) {
        int c = nt * 8 + 2 * t4;
        float v00 = O[nt][0] * inv0, v01 = O[nt][1] * inv0;
        float v10 = O[nt][2] * inv1, v11 = O[nt][3] * inv1;
        __nv_bfloat16 h00 = __float2bfloat16(v00), h01 = __float2bfloat16(v01);
        __nv_bfloat16 h10 = __float2bfloat16(v10), h11 = __float2bfloat16(v11);
        *(u32*)&g_ctxh[base0 + c] = pk2(h00, h01);
        *(u32*)&g_ctxl[base0 + c] = pk2f(v00 - __bfloat162float(h00), v01 - __bfloat162float(h01));
        *(u32*)&g_ctxh[base1 + c] = pk2(h10, h11);
        *(u32*)&g_ctxl[base1 + c] = pk2f(v10 - __bfloat162float(h10), v11 - __bfloat162float(h11));
    }
}

// ---------------- host launch ----------------
extern "C" void kernel_launch(void* const* d_in, const int* in_sizes, int n_in,
                              void* d_out, int out_size)
{
    const float* x            = (const float*)d_in[0];
    const float* kv_down_w    = (const float*)d_in[2];
    const float* kv_down_b    = (const float*)d_in[3];
    const float* key_up_w     = (const float*)d_in[4];
    const float* key_up_b     = (const float*)d_in[5];
    const float* value_up_w   = (const float*)d_in[6];
    const float* value_up_b   = (const float*)d_in[7];
    const float* key_rope_w   = (const float*)d_in[8];
    const float* key_rope_b   = (const float*)d_in[9];
    const float* query_down_w = (const float*)d_in[10];
    const float* query_down_b = (const float*)d_in[11];
    const float* query_up_w   = (const float*)d_in[12];
    const float* query_up_b   = (const float*)d_in[13];
    const float* query_rope_w = (const float*)d_in[14];
    const float* query_rope_b = (const float*)d_in[15];
    const float* out_w        = (const float*)d_in[16];
    const float* out_b        = (const float*)d_in[17];
    float* out = (float*)d_out;

    float *p_kc, *p_v, *p_kr, *p_quc, *p_qr;
    cudaGetSymbolAddress((void**)&p_kc,  g_kc);
    cudaGetSymbolAddress((void**)&p_v,   g_v);
    cudaGetSymbolAddress((void**)&p_kr,  g_kr);
    cudaGetSymbolAddress((void**)&p_quc, g_quc);
    cudaGetSymbolAddress((void**)&p_qr,  g_qr);
    __nv_bfloat16 *p_xh, *p_xl, *p_kvch, *p_kvcl, *p_qch, *p_qcl, *p_ctxh, *p_ctxl;
    cudaGetSymbolAddress((void**)&p_xh,   g_xh);
    cudaGetSymbolAddress((void**)&p_xl,   g_xl);
    cudaGetSymbolAddress((void**)&p_kvch, g_kvch);
    cudaGetSymbolAddress((void**)&p_kvcl, g_kvcl);
    cudaGetSymbolAddress((void**)&p_qch,  g_qch);
    cudaGetSymbolAddress((void**)&p_qcl,  g_qcl);
    cudaGetSymbolAddress((void**)&p_ctxh, g_ctxh);
    cudaGetSymbolAddress((void**)&p_ctxl, g_ctxl);

    // launch 0: prep
    {
        WP p;
        p.d[0] = { kv_down_w,    OFF_KVD, HIDDEN, KVC   };
        p.d[1] = { query_down_w, OFF_QD,  HIDDEN, QC    };
        p.d[2] = { key_up_w,     OFF_KU,  KVC,    NH*HD };
        p.d[3] = { value_up_w,   OFF_VU,  KVC,    NH*HD };
        p.d[4] = { key_rope_w,   OFF_KR,  KVC,    NH*RD };
        p.d[5] = { query_up_w,   OFF_QU,  QC,     NH*HD };
        p.d[6] = { query_rope_w, OFF_QR,  QC,     NH*RD };
        p.d[7] = { out_w,        OFF_OUT, NH*HD,  HIDDEN};
        prep_kernel<<<dim3(4096, 1, 10), 256>>>(p, x);
    }

    GSeg z = { 0, 0, 0, 0, 0, 0, 0, 0, 0 };
    size_t gsm = 2 * 4 * GBUF * 4;
    cudaFuncSetAttribute(hgemm_multi, cudaFuncAttributeMaxDynamicSharedMemorySize, (int)gsm);

    // launch 1: x -> kv_c || q_c
    {
        GP p;
        p.s[0] = { p_xh, p_xl, OFF_KVD, kv_down_b,    0, p_kvch, p_kvcl, KVC, HIDDEN };
        p.s[1] = { p_xh, p_xl, OFF_QD,  query_down_b, 0, p_qch,  p_qcl,  QC,  HIDDEN };
        p.s[2] = z; p.s[3] = z; p.s[4] = z;
        hgemm_multi<<<dim3((KVC+QC)/128, MR/128), 256, gsm>>>(p);
    }
    // launch 2 (merged): kv_c -> K/V/Kr  and  q_c -> Qc/Qr
    {
        GP p;
        p.s[0] = { p_kvch, p_kvcl, OFF_KU, key_up_b,     p_kc,  0, 0, NH*HD, KVC };
        p.s[1] = { p_kvch, p_kvcl, OFF_VU, value_up_b,   p_v,   0, 0, NH*HD, KVC };
        p.s[2] = { p_kvch, p_kvcl, OFF_KR, key_rope_b,   p_kr,  0, 0, NH*RD, KVC };
        p.s[3] = { p_qch,  p_qcl,  OFF_QU, query_up_b,   p_quc, 0, 0, NH*HD, QC  };
        p.s[4] = { p_qch,  p_qcl,  OFF_QR, query_rope_b, p_qr,  0, 0, NH*RD, QC  };
        hgemm_multi<<<dim3((3*NH*HD + 2*NH*RD)/128, MR/128), 256, gsm>>>(p);
    }
    // launch 3: pack K/Q/V
    {
        long long total = (long long)BHN * SEQ * AD;
        int blocks = (int)((total + 255) / 256);
        pack_all<<<dim3(blocks, 3), 256>>>();
    }
    // launch 4: attention
    cudaFuncSetAttribute(attn_mma_kernel, cudaFuncAttributeMaxDynamicSharedMemorySize, ATSM * 4);
    attn_mma_kernel<<<dim3(SEQ/128, BHN), 256, ATSM * 4>>>();

    // launch 5: out projection
    {
        GP p;
        p.s[0] = { p_ctxh, p_ctxl, OFF_OUT, out_b, out, 0, 0, HIDDEN, NH*HD };
        p.s[1] = z; p.s[2] = z; p.s[3] = z; p.s[4] = z;
        hgemm_multi<<<dim3(HIDDEN/128, MR/128), 256, gsm>>>(p);
    }
}

// round 16
// speedup vs baseline: 1.0727x; 1.0727x over previous
#include <cuda_runtime.h>
#include <cuda_bf16.h>
#include <math.h>
#include <stdint.h>

typedef unsigned int u32;

#define HIDDEN 2048
#define NH     16
#define HD     128
#define KVC    512
#define QC     1536
#define RD     64
#define BATCH  2
#define SEQ    2048
#define AD     192
#define MR     (BATCH*SEQ)
#define BHN    (BATCH*NH)

// ---------------- scratch ----------------
__device__ float g_kc  [MR*NH*HD];
__device__ float g_v   [MR*NH*HD];
__device__ float g_kr  [MR*NH*RD];
__device__ float g_quc [MR*NH*HD];
__device__ float g_qr  [MR*NH*RD];
__device__ float g_sinT[SEQ*32];
__device__ float g_cosT[SEQ*32];

__device__ __nv_bfloat16 g_xh  [(size_t)MR*HIDDEN];
__device__ __nv_bfloat16 g_xl  [(size_t)MR*HIDDEN];
__device__ __nv_bfloat16 g_kvch[(size_t)MR*KVC];
__device__ __nv_bfloat16 g_kvcl[(size_t)MR*KVC];
__device__ __nv_bfloat16 g_qch [(size_t)MR*QC];
__device__ __nv_bfloat16 g_qcl [(size_t)MR*QC];
__device__ __nv_bfloat16 g_ctxh[(size_t)MR*NH*HD];
__device__ __nv_bfloat16 g_ctxl[(size_t)MR*NH*HD];

#define WT_TOTAL 15728640
__device__ __nv_bfloat16 g_Wth[WT_TOTAL];
__device__ __nv_bfloat16 g_Wtl[WT_TOTAL];
#define OFF_KVD 0L
#define OFF_QD  1048576L
#define OFF_KU  4194304L
#define OFF_VU  5242880L
#define OFF_KR  6291456L
#define OFF_QU  6815744L
#define OFF_QR  9961472L
#define OFF_OUT 11534336L

__device__ __nv_bfloat16 g_Qph[(size_t)BHN*SEQ*AD];
__device__ __nv_bfloat16 g_Qpl[(size_t)BHN*SEQ*AD];
__device__ __nv_bfloat16 g_Kph[(size_t)BHN*SEQ*AD];
__device__ __nv_bfloat16 g_Kpl[(size_t)BHN*SEQ*AD];
__device__ u32 g_Vph[(size_t)BHN*HD*(SEQ/2)];
__device__ u32 g_Vpl[(size_t)BHN*HD*(SEQ/2)];

// ---------------- helpers ----------------
__device__ __forceinline__ float fexp(float x) {
    if (x < -80.f) return 0.f;
    float y = x * 1.4426950408889634f;
    float r = rintf(y);
    float f = y - r;
    float p = 1.3333558e-3f;
    p = fmaf(p, f, 9.6181291e-3f);
    p = fmaf(p, f, 5.5504109e-2f);
    p = fmaf(p, f, 2.4022651e-1f);
    p = fmaf(p, f, 6.9314718e-1f);
    p = fmaf(p, f, 1.0f);
    int n = (int)r;
    return p * __int_as_float((n + 127) << 23);
}
__device__ __forceinline__ u32 pk2(__nv_bfloat16 a, __nv_bfloat16 b) {
    return (u32)__bfloat16_as_ushort(a) | ((u32)__bfloat16_as_ushort(b) << 16);
}
__device__ __forceinline__ u32 pk2f(float a, float b) {
    return pk2(__float2bfloat16(a), __float2bfloat16(b));
}
__device__ __forceinline__ void mma_bf16(float* c, const u32* a, const u32* b) {
    asm volatile(
        "mma.sync.aligned.m16n8k16.row.col.f32.bf16.bf16.f32 "
        "{%0,%1,%2,%3}, {%4,%5,%6,%7}, {%8,%9}, {%0,%1,%2,%3};"
        : "+f"(c[0]), "+f"(c[1]), "+f"(c[2]), "+f"(c[3])
        : "r"(a[0]), "r"(a[1]), "r"(a[2]), "r"(a[3]), "r"(b[0]), "r"(b[1]));
}
__device__ __forceinline__ void ldm4(u32* r, u32 saddr) {
    asm volatile("ldmatrix.sync.aligned.m8n8.x4.shared.b16 {%0,%1,%2,%3}, [%4];"
        : "=r"(r[0]), "=r"(r[1]), "=r"(r[2]), "=r"(r[3]) : "r"(saddr));
}
__device__ __forceinline__ u32 smem_u32p(const void* p) {
    u32 a;
    asm("{ .reg .u64 t; cvta.to.shared.u64 t, %1; cvt.u32.u64 %0, t; }" : "=r"(a) : "l"(p));
    return a;
}
__device__ __forceinline__ void cpa16(u32 s, const void* g) {
    asm volatile("cp.async.cg.shared.global [%0], [%1], 16;" :: "r"(s), "l"(g));
}
#define CPC()  asm volatile("cp.async.commit_group;" ::: "memory")
#define CPW0() asm volatile("cp.async.wait_group 0;" ::: "memory")

// ---------------- prep ----------------
struct WD { const float* src; long off; int K; int N; };
struct WP { WD d[8]; };

__global__ void prep_kernel(WP p, const float* __restrict__ x) {
    int z = blockIdx.z;
    if (z < 8) {
        WD d = p.d[z];
        int ktiles = d.K >> 5, ntiles = d.N >> 5;
        int tile = blockIdx.x;
        if (tile >= ktiles * ntiles) return;
        int k0 = (tile % ktiles) << 5;
        int n0 = (tile / ktiles) << 5;
        __shared__ float tb[32][33];
        int lx = threadIdx.x & 31, ly = threadIdx.x >> 5;
        for (int i = ly; i < 32; i += 8)
            tb[i][lx] = d.src[(size_t)(k0 + i) * d.N + n0 + lx];
        __syncthreads();
        for (int i = ly; i < 32; i += 8) {
            float v = tb[lx][i];
            __nv_bfloat16 hi = __float2bfloat16(v);
            size_t o = d.off + (size_t)(n0 + i) * d.K + k0 + lx;
            g_Wth[o] = hi;
            g_Wtl[o] = __float2bfloat16(v - __bfloat162float(hi));
        }
    } else if (z == 8) {
        for (long long i = (long long)blockIdx.x * 256 + threadIdx.x;
             i < (long long)MR * HIDDEN; i += 4096LL * 256) {
            float v = x[i];
            __nv_bfloat16 hi = __float2bfloat16(v);
            g_xh[i] = hi;
            g_xl[i] = __float2bfloat16(v - __bfloat162float(hi));
        }
    } else {
        int i = blockIdx.x * 256 + threadIdx.x;
        if (i < SEQ * 32) {
            int s = i >> 5, pp = i & 31;
            double inv = pow(10000.0, -((double)pp) / 32.0);
            double a = (double)s * inv;
            g_sinT[i] = (float)sin(a);
            g_cosT[i] = (float)cos(a);
        }
    }
}

// ---------------- bf16-split HMMA multi-segment GEMM ----------------
struct GSeg {
    const __nv_bfloat16* aph; const __nv_bfloat16* apl;
    long woff; const float* bias;
    float* outf; __nv_bfloat16* oh; __nv_bfloat16* ol;
    int N; int K;
};
struct GP { GSeg s[5]; };

#define GBUF 2560   // 128 rows * 20 u32

__global__ __launch_bounds__(256, 2) void hgemm_multi(GP p)
{
    extern __shared__ u32 smg[];
    const u32 sb = smem_u32p(smg);
    const int tid = threadIdx.x, lane = tid & 31, w = tid >> 5;
    const int wm = w & 3, wn = w >> 2;
    const int g = lane >> 2, t = lane & 3;
    const int row0 = blockIdx.y * 128;
    int cg = blockIdx.x * 128;

    GSeg sg = p.s[0];
    int col0 = cg;
    #pragma unroll
    for (int i = 0; i < 5; i++) {
        if (p.s[i].N > 0 && col0 < p.s[i].N) { sg = p.s[i]; break; }
        col0 -= p.s[i].N;
    }
    const int K = sg.K;
    const __nv_bfloat16* Aph = sg.aph;
    const __nv_bfloat16* Apl = sg.apl;
    const __nv_bfloat16* Bph = g_Wth + sg.woff;
    const __nv_bfloat16* Bpl = g_Wtl + sg.woff;

    const int lr = tid >> 2;
    const int lc = (tid & 3) * 4;

    float acc[2][8][4];
    #pragma unroll
    for (int mt = 0; mt < 2; mt++)
        #pragma unroll
        for (int nt = 0; nt < 8; nt++)
            #pragma unroll
            for (int j = 0; j < 4; j++) acc[mt][nt][j] = 0.f;

    const u32 arow = wm * 32 + (lane & 15);
    const u32 aoff = ((lane >> 4) << 2);
    const u32 krow = (lane & 7) | ((lane >> 4) << 3);
    const u32 koff = ((lane >> 3) & 1) << 2;

    const int KT = K >> 5;

    // prologue: stage 0
    #pragma unroll
    for (int j = 0; j < 2; j++) {
        int r = lr + j * 64;
        u32 so = sb + (r * 20 + lc) * 4;
        cpa16(so,              Aph + (size_t)(row0 + r) * K + lc * 2);
        cpa16(so + GBUF * 4,   Apl + (size_t)(row0 + r) * K + lc * 2);
        cpa16(so + GBUF * 8,   Bph + (size_t)(col0 + r) * K + lc * 2);
        cpa16(so + GBUF * 12,  Bpl + (size_t)(col0 + r) * K + lc * 2);
    }
    CPC();

    for (int kt = 0; kt < KT; kt++) {
        CPW0();
        __syncthreads();
        if (kt + 1 < KT) {
            int k0 = (kt + 1) << 5;
            u32 stb = sb + ((kt + 1) & 1) * GBUF * 16;
            #pragma unroll
            for (int j = 0; j < 2; j++) {
                int r = lr + j * 64;
                u32 so = stb + (r * 20 + lc) * 4;
                cpa16(so,              Aph + (size_t)(row0 + r) * K + k0 + lc * 2);
                cpa16(so + GBUF * 4,   Apl + (size_t)(row0 + r) * K + k0 + lc * 2);
                cpa16(so + GBUF * 8,   Bph + (size_t)(col0 + r) * K + k0 + lc * 2);
                cpa16(so + GBUF * 12,  Bpl + (size_t)(col0 + r) * K + k0 + lc * 2);
            }
            CPC();
        }

        const u32 stb = sb + (kt & 1) * GBUF * 16;
        const u32 bA  = stb + (arow * 20 + aoff) * 4;
        const u32 bAl = bA + GBUF * 4;
        const u32 bB  = stb + GBUF * 8 + ((wn * 64 + krow) * 20 + koff) * 4;
        const u32 bBl = bB + GBUF * 4;

        #pragma unroll
        for (int ks = 0; ks < 2; ks++) {
            u32 ah[2][4], al[2][4];
            ldm4(ah[0], bA + ks * 32);
            ldm4(ah[1], bA + 1280 + ks * 32);
            ldm4(al[0], bAl + ks * 32);
            ldm4(al[1], bAl + 1280 + ks * 32);
            #pragma unroll
            for (int ntp = 0; ntp < 4; ntp++) {
                u32 bh[4], bl[4];
                ldm4(bh, bB + ntp * 1280 + ks * 32);
                ldm4(bl, bBl + ntp * 1280 + ks * 32);
                mma_bf16(acc[0][2*ntp],   ah[0], bh);
                mma_bf16(acc[1][2*ntp],   ah[1], bh);
                mma_bf16(acc[0][2*ntp+1], ah[0], bh + 2);
                mma_bf16(acc[1][2*ntp+1], ah[1], bh + 2);
                mma_bf16(acc[0][2*ntp],   ah[0], bl);
                mma_bf16(acc[1][2*ntp],   ah[1], bl);
                mma_bf16(acc[0][2*ntp+1], ah[0], bl + 2);
                mma_bf16(acc[1][2*ntp+1], ah[1], bl + 2);
                mma_bf16(acc[0][2*ntp],   al[0], bh);
                mma_bf16(acc[1][2*ntp],   al[1], bh);
                mma_bf16(acc[0][2*ntp+1], al[0], bh + 2);
                mma_bf16(acc[1][2*ntp+1], al[1], bh + 2);
            }
        }
    }

    // epilogue
    #pragma unroll
    for (int mt = 0; mt < 2; mt++) {
        int r0 = row0 + wm * 32 + mt * 16 + g;
        int r1 = r0 + 8;
        #pragma unroll
        for (int nt = 0; nt < 8; nt++) {
            int c = col0 + wn * 64 + nt * 8 + 2 * t;
            float b0 = sg.bias[c], b1 = sg.bias[c + 1];
            float v00 = acc[mt][nt][0] + b0, v01 = acc[mt][nt][1] + b1;
            float v10 = acc[mt][nt][2] + b0, v11 = acc[mt][nt][3] + b1;
            if (sg.outf) {
                float2 w0; w0.x = v00; w0.y = v01;
                float2 w1; w1.x = v10; w1.y = v11;
                *(float2*)&sg.outf[(size_t)r0 * sg.N + c] = w0;
                *(float2*)&sg.outf[(size_t)r1 * sg.N + c] = w1;
            } else {
                __nv_bfloat16 h00 = __float2bfloat16(v00), h01 = __float2bfloat16(v01);
                __nv_bfloat16 h10 = __float2bfloat16(v10), h11 = __float2bfloat16(v11);
                *(u32*)&sg.oh[(size_t)r0 * sg.N + c] = pk2(h00, h01);
                *(u32*)&sg.ol[(size_t)r0 * sg.N + c] =
                    pk2f(v00 - __bfloat162float(h00), v01 - __bfloat162float(h01));
                *(u32*)&sg.oh[(size_t)r1 * sg.N + c] = pk2(h10, h11);
                *(u32*)&sg.ol[(size_t)r1 * sg.N + c] =
                    pk2f(v10 - __bfloat162float(h10), v11 - __bfloat162float(h11));
            }
        }
    }
}

// ---------------- vectorized pack kernel (4 elems/thread; Q pre-scaled) ------------
#define QK_SCALE 0.07216878364870323f

__global__ void pack_all()
{
    int job = blockIdx.y;
    if (job < 2) {
        const float* cflat = job ? g_quc : g_kc;
        const float* rflat = job ? g_qr  : g_kr;
        uint2* oh = (uint2*)(job ? g_Qph : g_Kph);
        uint2* ol = (uint2*)(job ? g_Qpl : g_Kpl);
        long long idx = (long long)blockIdx.x * 256 + threadIdx.x;   // vec-4 index
        const long long total = (long long)BHN * SEQ * 48;
        if (idx >= total) return;
        int d4 = (int)(idx % 48) * 4;
        int s  = (int)((idx / 48) % SEQ);
        int h  = (int)((idx / (48LL * SEQ)) % NH);
        int b  = (int)(idx / (48LL * SEQ * NH));
        int row = b * SEQ + s;
        float v0, v1, v2, v3;
        if (d4 < HD) {
            float4 f = *(const float4*)&cflat[(size_t)row * (NH*HD) + h * HD + d4];
            v0 = f.x; v1 = f.y; v2 = f.z; v3 = f.w;
        } else {
            int j = d4 - HD;
            float4 f = *(const float4*)&rflat[(size_t)row * (NH*RD) + h * RD + j];
            int p = j >> 1;
            float c0 = g_cosT[s * 32 + p],     s0 = g_sinT[s * 32 + p];
            float c1 = g_cosT[s * 32 + p + 1], s1 = g_sinT[s * 32 + p + 1];
            v0 = f.x * c0 - f.y * s0;
            v1 = f.x * s0 + f.y * c0;
            v2 = f.z * c1 - f.w * s1;
            v3 = f.z * s1 + f.w * c1;
        }
        if (job) { v0 *= QK_SCALE; v1 *= QK_SCALE; v2 *= QK_SCALE; v3 *= QK_SCALE; }
        __nv_bfloat16 h0 = __float2bfloat16(v0), h1 = __float2bfloat16(v1);
        __nv_bfloat16 h2 = __float2bfloat16(v2), h3 = __float2bfloat16(v3);
        uint2 ho, lo;
        ho.x = pk2(h0, h1); ho.y = pk2(h2, h3);
        lo.x = pk2f(v0 - __bfloat162float(h0), v1 - __bfloat162float(h1));
        lo.y = pk2f(v2 - __bfloat162float(h2), v3 - __bfloat162float(h3));
        oh[idx] = ho;
        ol[idx] = lo;
    } else {
        int tile = blockIdx.x;
        if (tile >= 64 * 4 * BHN) return;
        int s0 = (tile & 63) * 32;
        int d0 = ((tile >> 6) & 3) * 32;
        int bh = tile >> 8;
        int b = bh >> 4, h = bh & 15;
        int lx = threadIdx.x & 31, ly = threadIdx.x >> 5;
        __shared__ float tilebuf[32][33];
        for (int i = ly; i < 32; i += 8) {
            int s = s0 + i;
            tilebuf[i][lx] = g_v[(size_t)(b * SEQ + s) * (NH*HD) + h * HD + d0 + lx];
        }
        __syncthreads();
        for (int i = ly; i < 32; i += 8) {
            if (lx < 16) {
                int d = d0 + i;
                float v0 = tilebuf[2 * lx][i];
                float v1 = tilebuf[2 * lx + 1][i];
                __nv_bfloat16 h0 = __float2bfloat16(v0);
                __nv_bfloat16 h1 = __float2bfloat16(v1);
                size_t o = ((size_t)bh * HD + d) * (SEQ/2) + (s0 >> 1) + lx;
                g_Vph[o] = pk2(h0, h1);
                g_Vpl[o] = pk2(__float2bfloat16(v0 - __bfloat162float(h0)),
                               __float2bfloat16(v1 - __bfloat162float(h1)));
            }
        }
    }
}

// ---------------- cp.async pipelined mma attention (BN=32) ----------------
#define ATQH 0
#define ATQL 12800
#define ATK  25600
#define ATV  38400
#define ATSM 48640

__global__ __launch_bounds__(256) void attn_mma_kernel()
{
    extern __shared__ u32 sm[];
    const u32 sb   = smem_u32p(sm);
    const int tid  = threadIdx.x;
    const int lane = tid & 31;
    const int w    = tid >> 5;
    const int g    = lane >> 2;
    const int t4   = lane & 3;
    const int qt   = (int)gridDim.x - 1 - (int)blockIdx.x;
    const int bh   = blockIdx.y;
    const int b    = bh >> 4, h = bh & 15;
    const int q0   = qt * 128;
    const int T    = 4 * qt + 4;

    const uint4* Qh4 = (const uint4*)g_Qph;
    const uint4* Ql4 = (const uint4*)g_Qpl;
    const uint4* Kh4 = (const uint4*)g_Kph;
    const uint4* Kl4 = (const uint4*)g_Kpl;

    for (int i = tid; i < 3072; i += 256) {
        int r = i / 24, c = i - r * 24;
        size_t gs = ((size_t)bh * SEQ + q0 + r) * 24 + c;
        *(uint4*)&sm[ATQH + r * 100 + c * 4] = Qh4[gs];
        *(uint4*)&sm[ATQL + r * 100 + c * 4] = Ql4[gs];
    }

    {
        #pragma unroll
        for (int j = 0; j < 3; j++) {
            int i = tid + j * 256;
            int r = i / 24, c = i - r * 24;
            u32 so = sb + (ATK + r * 100 + c * 4) * 4;
            cpa16(so,            &Kh4[((size_t)bh * SEQ + r) * 24 + c]);
            cpa16(so + 3200 * 4, &Kl4[((size_t)bh * SEQ + r) * 24 + c]);
        }
        #pragma unroll
        for (int j = 0; j < 2; j++) {
            int i = tid + j * 256;
            int r = i >> 2, c = i & 3;
            u32 so = sb + (ATV + r * 20 + c * 4) * 4;
            cpa16(so,            &g_Vph[(((size_t)bh * HD + r) * 256 + c) * 4]);
            cpa16(so + 2560 * 4, &g_Vpl[(((size_t)bh * HD + r) * 256 + c) * 4]);
        }
        CPC();
    }

    const u32 qrow = w * 16 + (lane & 15);
    const u32 qoff = (lane >> 4) << 2;
    const u32 aQh = sb + (ATQH + qrow * 100 + qoff) * 4;
    const u32 aQl = sb + (ATQL + qrow * 100 + qoff) * 4;
    const u32 krow = (lane & 7) | ((lane >> 4) << 3);
    const u32 koff = ((lane >> 3) & 1) << 2;

    float m0 = -1e30f, m1 = -1e30f, l0 = 0.f, l1 = 0.f;
    float O[16][4];
    #pragma unroll
    for (int nt = 0; nt < 16; nt++)
        #pragma unroll
        for (int j = 0; j < 4; j++) O[nt][j] = 0.f;

    const int row0g = q0 + w * 16 + g;
    const int row1g = row0g + 8;
    const int wrow_max = q0 + w * 16 + 15;

    for (int kt = 0; kt < T; kt++) {
        CPW0();
        __syncthreads();
        if (kt + 1 < T) {
            int kn = (kt + 1) * 32;
            u32 skb = sb + (ATK + ((kt + 1) & 1) * 6400) * 4;
            u32 svb = sb + (ATV + ((kt + 1) & 1) * 5120) * 4;
            #pragma unroll
            for (int j = 0; j < 3; j++) {
                int i = tid + j * 256;
                int r = i / 24, c = i - r * 24;
                u32 so = skb + (r * 100 + c * 4) * 4;
                cpa16(so,            &Kh4[((size_t)bh * SEQ + kn + r) * 24 + c]);
                cpa16(so + 3200 * 4, &Kl4[((size_t)bh * SEQ + kn + r) * 24 + c]);
            }
            #pragma unroll
            for (int j = 0; j < 2; j++) {
                int i = tid + j * 256;
                int r = i >> 2, c = i & 3;
                u32 so = svb + (r * 20 + c * 4) * 4;
                cpa16(so,            &g_Vph[((size_t)bh * HD + r) * 1024 + (kt + 1) * 16 + c * 4]);
                cpa16(so + 2560 * 4, &g_Vpl[((size_t)bh * HD + r) * 1024 + (kt + 1) * 16 + c * 4]);
            }
            CPC();
        }

        const int k0 = kt * 32;
        if (k0 > wrow_max) continue;
        const int ng = min(2, (wrow_max - k0) / 16 + 1);

        const u32 aK  = sb + (ATK + (kt & 1) * 6400 + krow * 100 + koff) * 4;
        const u32 aKl = aK + 3200 * 4;
        const u32 aV  = sb + (ATV + (kt & 1) * 5120 + krow * 20 + koff) * 4;
        const u32 aVl = aV + 2560 * 4;

        float sc[4][4];
        #pragma unroll
        for (int nt = 0; nt < 4; nt++)
            #pragma unroll
            for (int j = 0; j < 4; j++) sc[nt][j] = 0.f;

        if (ng == 2) {
            #pragma unroll
            for (int ks = 0; ks < 12; ks++) {
                u32 ah[4], al[4];
                ldm4(ah, aQh + ks * 32);
                ldm4(al, aQl + ks * 32);
                #pragma unroll
                for (int ntp = 0; ntp < 2; ntp++) {
                    u32 kh[4], kl[4];
                    ldm4(kh, aK + ntp * 6400 + ks * 32);
                    ldm4(kl, aKl + ntp * 6400 + ks * 32);
                    mma_bf16(sc[2*ntp],   ah, kh);
                    mma_bf16(sc[2*ntp+1], ah, kh + 2);
                    mma_bf16(sc[2*ntp],   ah, kl);
                    mma_bf16(sc[2*ntp+1], ah, kl + 2);
                    mma_bf16(sc[2*ntp],   al, kh);
                    mma_bf16(sc[2*ntp+1], al, kh + 2);
                }
            }
        } else {
            #pragma unroll
            for (int ks = 0; ks < 12; ks++) {
                u32 ah[4], al[4];
                ldm4(ah, aQh + ks * 32);
                ldm4(al, aQl + ks * 32);
                u32 kh[4], kl[4];
                ldm4(kh, aK + ks * 32);
                ldm4(kl, aKl + ks * 32);
                mma_bf16(sc[0], ah, kh);
                mma_bf16(sc[1], ah, kh + 2);
                mma_bf16(sc[0], ah, kl);
                mma_bf16(sc[1], ah, kl + 2);
                mma_bf16(sc[0], al, kh);
                mma_bf16(sc[1], al, kh + 2);
            }
        }

        const bool diag = (k0 + 31) > row0g;
        float mt0 = -1e30f, mt1 = -1e30f;
        #pragma unroll
        for (int nt = 0; nt < 4; nt++) {
            int c0 = k0 + nt * 8 + 2 * t4, c1 = c0 + 1;
            if (diag) {
                if (c0 > row0g) sc[nt][0] = -1e30f;
                if (c1 > row0g) sc[nt][1] = -1e30f;
                if (c0 > row1g) sc[nt][2] = -1e30f;
                if (c1 > row1g) sc[nt][3] = -1e30f;
            }
            mt0 = fmaxf(mt0, fmaxf(sc[nt][0], sc[nt][1]));
            mt1 = fmaxf(mt1, fmaxf(sc[nt][2], sc[nt][3]));
        }
        mt0 = fmaxf(mt0, __shfl_xor_sync(0xffffffffu, mt0, 1));
        mt0 = fmaxf(mt0, __shfl_xor_sync(0xffffffffu, mt0, 2));
        mt1 = fmaxf(mt1, __shfl_xor_sync(0xffffffffu, mt1, 1));
        mt1 = fmaxf(mt1, __shfl_xor_sync(0xffffffffu, mt1, 2));

        float mn0 = fmaxf(m0, mt0), mn1 = fmaxf(m1, mt1);
        float a0 = fexp(m0 - mn0), a1 = fexp(m1 - mn1);
        m0 = mn0; m1 = mn1;

        float s0 = 0.f, s1 = 0.f;
        #pragma unroll
        for (int nt = 0; nt < 4; nt++) {
            sc[nt][0] = fexp(sc[nt][0] - mn0);
            sc[nt][1] = fexp(sc[nt][1] - mn0);
            sc[nt][2] = fexp(sc[nt][2] - mn1);
            sc[nt][3] = fexp(sc[nt][3] - mn1);
            s0 += sc[nt][0] + sc[nt][1];
            s1 += sc[nt][2] + sc[nt][3];
        }
        s0 += __shfl_xor_sync(0xffffffffu, s0, 1);
        s0 += __shfl_xor_sync(0xffffffffu, s0, 2);
        s1 += __shfl_xor_sync(0xffffffffu, s1, 1);
        s1 += __shfl_xor_sync(0xffffffffu, s1, 2);
        l0 = l0 * a0 + s0;
        l1 = l1 * a1 + s1;

        #pragma unroll
        for (int nt = 0; nt < 16; nt++) {
            O[nt][0] *= a0; O[nt][1] *= a0;
            O[nt][2] *= a1; O[nt][3] *= a1;
        }

        #pragma unroll
        for (int ks = 0; ks < 2; ks++) {
            if (ks >= ng) break;
            u32 ah[4], al[4];
            #pragma unroll
            for (int half = 0; half < 2; half++) {
                float v0 = sc[2*ks + half][0], v1 = sc[2*ks + half][1];
                float v2 = sc[2*ks + half][2], v3 = sc[2*ks + half][3];
                __nv_bfloat16 h0 = __float2bfloat16(v0), h1 = __float2bfloat16(v1);
                __nv_bfloat16 h2 = __float2bfloat16(v2), h3 = __float2bfloat16(v3);
                ah[half*2 + 0] = pk2(h0, h1);
                ah[half*2 + 1] = pk2(h2, h3);
                al[half*2 + 0] = pk2f(v0 - __bfloat162float(h0), v1 - __bfloat162float(h1));
                al[half*2 + 1] = pk2f(v2 - __bfloat162float(h2), v3 - __bfloat162float(h3));
            }
            #pragma unroll
            for (int ntp = 0; ntp < 8; ntp++) {
                u32 vh[4], vl[4];
                ldm4(vh, aV + ntp * 1280 + ks * 32);
                ldm4(vl, aVl + ntp * 1280 + ks * 32);
                mma_bf16(O[2*ntp],   ah, vh);
                mma_bf16(O[2*ntp+1], ah, vh + 2);
                mma_bf16(O[2*ntp],   ah, vl);
                mma_bf16(O[2*ntp+1], ah, vl + 2);
                mma_bf16(O[2*ntp],   al, vh);
                mma_bf16(O[2*ntp+1], al, vh + 2);
            }
        }
    }

    // ---- epilogue ----
    float inv0 = 1.f / l0, inv1 = 1.f / l1;
    size_t base0 = ((size_t)(b * SEQ) + row0g) * (NH*HD) + h * HD;
    size_t base1 = ((size_t)(b * SEQ) + row1g) * (NH*HD) + h * HD;
    #pragma unroll
    for (int nt = 0; nt < 16; nt++) {
        int c = nt * 8 + 2 * t4;
        float v00 = O[nt][0] * inv0, v01 = O[nt][1] * inv0;
        float v10 = O[nt][2] * inv1, v11 = O[nt][3] * inv1;
        __nv_bfloat16 h00 = __float2bfloat16(v00), h01 = __float2bfloat16(v01);
        __nv_bfloat16 h10 = __float2bfloat16(v10), h11 = __float2bfloat16(v11);
        *(u32*)&g_ctxh[base0 + c] = pk2(h00, h01);
        *(u32*)&g_ctxl[base0 + c] = pk2f(v00 - __bfloat162float(h00), v01 - __bfloat162float(h01));
        *(u32*)&g_ctxh[base1 + c] = pk2(h10, h11);
        *(u32*)&g_ctxl[base1 + c] = pk2f(v10 - __bfloat162float(h10), v11 - __bfloat162float(h11));
    }
}

// ---------------- host launch ----------------
extern "C" void kernel_launch(void* const* d_in, const int* in_sizes, int n_in,
                              void* d_out, int out_size)
{
    const float* x            = (const float*)d_in[0];
    const float* kv_down_w    = (const float*)d_in[2];
    const float* kv_down_b    = (const float*)d_in[3];
    const float* key_up_w     = (const float*)d_in[4];
    const float* key_up_b     = (const float*)d_in[5];
    const float* value_up_w   = (const float*)d_in[6];
    const float* value_up_b   = (const float*)d_in[7];
    const float* key_rope_w   = (const float*)d_in[8];
    const float* key_rope_b   = (const float*)d_in[9];
    const float* query_down_w = (const float*)d_in[10];
    const float* query_down_b = (const float*)d_in[11];
    const float* query_up_w   = (const float*)d_in[12];
    const float* query_up_b   = (const float*)d_in[13];
    const float* query_rope_w = (const float*)d_in[14];
    const float* query_rope_b = (const float*)d_in[15];
    const float* out_w        = (const float*)d_in[16];
    const float* out_b        = (const float*)d_in[17];
    float* out = (float*)d_out;

    float *p_kc, *p_v, *p_kr, *p_quc, *p_qr;
    cudaGetSymbolAddress((void**)&p_kc,  g_kc);
    cudaGetSymbolAddress((void**)&p_v,   g_v);
    cudaGetSymbolAddress((void**)&p_kr,  g_kr);
    cudaGetSymbolAddress((void**)&p_quc, g_quc);
    cudaGetSymbolAddress((void**)&p_qr,  g_qr);
    __nv_bfloat16 *p_xh, *p_xl, *p_kvch, *p_kvcl, *p_qch, *p_qcl, *p_ctxh, *p_ctxl;
    cudaGetSymbolAddress((void**)&p_xh,   g_xh);
    cudaGetSymbolAddress((void**)&p_xl,   g_xl);
    cudaGetSymbolAddress((void**)&p_kvch, g_kvch);
    cudaGetSymbolAddress((void**)&p_kvcl, g_kvcl);
    cudaGetSymbolAddress((void**)&p_qch,  g_qch);
    cudaGetSymbolAddress((void**)&p_qcl,  g_qcl);
    cudaGetSymbolAddress((void**)&p_ctxh, g_ctxh);
    cudaGetSymbolAddress((void**)&p_ctxl, g_ctxl);

    // launch 0: prep
    {
        WP p;
        p.d[0] = { kv_down_w,    OFF_KVD, HIDDEN, KVC   };
        p.d[1] = { query_down_w, OFF_QD,  HIDDEN, QC    };
        p.d[2] = { key_up_w,     OFF_KU,  KVC,    NH*HD };
        p.d[3] = { value_up_w,   OFF_VU,  KVC,    NH*HD };
        p.d[4] = { key_rope_w,   OFF_KR,  KVC,    NH*RD };
        p.d[5] = { query_up_w,   OFF_QU,  QC,     NH*HD };
        p.d[6] = { query_rope_w, OFF_QR,  QC,     NH*RD };
        p.d[7] = { out_w,        OFF_OUT, NH*HD,  HIDDEN};
        prep_kernel<<<dim3(4096, 1, 10), 256>>>(p, x);
    }

    GSeg z = { 0, 0, 0, 0, 0, 0, 0, 0, 0 };
    size_t gsm = 2 * 4 * GBUF * 4;
    cudaFuncSetAttribute(hgemm_multi, cudaFuncAttributeMaxDynamicSharedMemorySize, (int)gsm);

    // launch 1: x -> kv_c || q_c
    {
        GP p;
        p.s[0] = { p_xh, p_xl, OFF_KVD, kv_down_b,    0, p_kvch, p_kvcl, KVC, HIDDEN };
        p.s[1] = { p_xh, p_xl, OFF_QD,  query_down_b, 0, p_qch,  p_qcl,  QC,  HIDDEN };
        p.s[2] = z; p.s[3] = z; p.s[4] = z;
        hgemm_multi<<<dim3((KVC+QC)/128, MR/128), 256, gsm>>>(p);
    }
    // launch 2 (merged, heavy-K segments first for wave balance)
    {
        GP p;
        p.s[0] = { p_qch,  p_qcl,  OFF_QU, query_up_b,   p_quc, 0, 0, NH*HD, QC  };
        p.s[1] = { p_qch,  p_qcl,  OFF_QR, query_rope_b, p_qr,  0, 0, NH*RD, QC  };
        p.s[2] = { p_kvch, p_kvcl, OFF_KU, key_up_b,     p_kc,  0, 0, NH*HD, KVC };
        p.s[3] = { p_kvch, p_kvcl, OFF_VU, value_up_b,   p_v,   0, 0, NH*HD, KVC };
        p.s[4] = { p_kvch, p_kvcl, OFF_KR, key_rope_b,   p_kr,  0, 0, NH*RD, KVC };
        hgemm_multi<<<dim3((3*NH*HD + 2*NH*RD)/128, MR/128), 256, gsm>>>(p);
    }
    // launch 3: pack K/Q/V (vectorized)
    pack_all<<<dim3(12288, 3), 256>>>();

    // launch 4: attention
    cudaFuncSetAttribute(attn_mma_kernel, cudaFuncAttributeMaxDynamicSharedMemorySize, ATSM * 4);
    attn_mma_kernel<<<dim3(SEQ/128, BHN), 256, ATSM * 4>>>();

    // launch 5: out projection
    {
        GP p;
        p.s[0] = { p_ctxh, p_ctxl, OFF_OUT, out_b, out, 0, 0, HIDDEN, NH*HD };
        p.s[1] = z; p.s[2] = z; p.s[3] = z; p.s[4] = z;
        hgemm_multi<<<dim3(HIDDEN/128, MR/128), 256, gsm>>>(p);
    }
}